// round 1
// baseline (speedup 1.0000x reference)
#include <cuda_runtime.h>
#include <cuda_bf16.h>

// Problem shapes (fixed by the dataset):
//   text:        [16, 2048, 256] f32      d_in[0]
//   const_mat:   [16, 2048, 2048] i32     d_in[1]   (UNUSED: softmax rows sum to 1)
//   const_labels:[16, 2048, 8] i32        d_in[2]
//   emb_table:   [100, 128] f32           d_in[3]
//   attn_W:      [256, 384] f32           d_in[4]   (UNUSED: cancels in softmax)
//   attn_b:      [256] f32                d_in[5]   (UNUSED)
//   fc_W:        [256, 128] f32           d_in[6]
//   fc_b:        [256] f32                d_in[7]
//   out:         [16, 2048, 256] f32
//
// Math: out[b,i,:] = relu( text[b,i,:] + mean_k emb_table[labels[b,i,k]] @ fc_W^T + fc_b )
// Precompute G[n,d] = (sum_c emb_table[n,c]*fc_W[d,c] + fc_b[d]) / 8, then
//   out[pos,d] = relu( text[pos,d] + sum_{k=0..7} G[labels[pos,k], d] )

#define CN   100
#define CD   128
#define DIM  256
#define KLBL 8
#define NPOS (16 * 2048)

__device__ float g_G[CN * DIM];  // 100 KB scratch table

// ---------------------------------------------------------------------------
// Kernel A: build G[n,d] = 0.125 * (fc_b[d] + sum_c emb_table[n,c] * fc_W[d,c])
// grid = CN blocks, block = DIM threads
// ---------------------------------------------------------------------------
__global__ void __launch_bounds__(DIM) build_G_kernel(
    const float* __restrict__ emb_table,
    const float* __restrict__ fc_W,
    const float* __restrict__ fc_b)
{
    __shared__ float se[CD];
    const int n = blockIdx.x;
    const int d = threadIdx.x;
    if (d < CD) se[d] = emb_table[n * CD + d];
    __syncthreads();

    const float4* w4 = reinterpret_cast<const float4*>(fc_W + d * CD);
    float acc = fc_b[d];
    #pragma unroll
    for (int c4 = 0; c4 < CD / 4; c4++) {
        float4 w = w4[c4];
        acc = fmaf(se[c4 * 4 + 0], w.x, acc);
        acc = fmaf(se[c4 * 4 + 1], w.y, acc);
        acc = fmaf(se[c4 * 4 + 2], w.z, acc);
        acc = fmaf(se[c4 * 4 + 3], w.w, acc);
    }
    g_G[n * DIM + d] = 0.125f * acc;
}

// ---------------------------------------------------------------------------
// Kernel B: fused gather-add-relu.
// G table staged in dynamic shared memory (102,400 bytes).
// block = 512 threads => processes 2 positions per iteration.
// grid = 148 (one CTA per SM; grid-stride over positions).
// ---------------------------------------------------------------------------
__global__ void __launch_bounds__(512) fused_gather_kernel(
    const float* __restrict__ text,
    const int*   __restrict__ labels,
    float*       __restrict__ out,
    int npos)
{
    extern __shared__ float sG[];  // CN*DIM floats

    // Stage G into shared memory (6400 float4 loads).
    const float4* G4 = reinterpret_cast<const float4*>(g_G);
    float4* sG4 = reinterpret_cast<float4*>(sG);
    for (int i = threadIdx.x; i < (CN * DIM) / 4; i += blockDim.x)
        sG4[i] = G4[i];
    __syncthreads();

    const int d   = threadIdx.x & (DIM - 1);   // 0..255
    const int sub = threadIdx.x >> 8;          // 0..1
    const int posPerIter = blockDim.x >> 8;    // 2
    const int stride = gridDim.x * posPerIter;

    for (int pos = blockIdx.x * posPerIter + sub; pos < npos; pos += stride) {
        // 8 labels = two int4 loads (32B-aligned: pos*8*4 bytes)
        const int4* lb = reinterpret_cast<const int4*>(labels + pos * KLBL);
        int4 l0 = lb[0];
        int4 l1 = lb[1];

        float a0 = text[pos * DIM + d];
        float a1 = 0.0f;
        a0 += sG[l0.x * DIM + d];
        a1 += sG[l0.y * DIM + d];
        a0 += sG[l0.z * DIM + d];
        a1 += sG[l0.w * DIM + d];
        a0 += sG[l1.x * DIM + d];
        a1 += sG[l1.y * DIM + d];
        a0 += sG[l1.z * DIM + d];
        a1 += sG[l1.w * DIM + d];

        out[pos * DIM + d] = fmaxf(a0 + a1, 0.0f);
    }
}

// ---------------------------------------------------------------------------
extern "C" void kernel_launch(void* const* d_in, const int* in_sizes, int n_in,
                              void* d_out, int out_size)
{
    const float* text      = (const float*)d_in[0];
    const int*   labels    = (const int*)  d_in[2];
    const float* emb_table = (const float*)d_in[3];
    const float* fc_W      = (const float*)d_in[6];
    const float* fc_b      = (const float*)d_in[7];
    float*       out       = (float*)d_out;

    const int npos = in_sizes[0] / DIM;  // 32768

    // Opt-in to >48KB dynamic shared memory (idempotent; not a stream op,
    // safe under graph capture).
    const int smemBytes = CN * DIM * (int)sizeof(float);  // 102400
    cudaFuncSetAttribute(fused_gather_kernel,
                         cudaFuncAttributeMaxDynamicSharedMemorySize, smemBytes);

    build_G_kernel<<<CN, DIM>>>(emb_table, fc_W, fc_b);
    fused_gather_kernel<<<148, 512, smemBytes>>>(text, labels, out, npos);
}

// round 2
// speedup vs baseline: 1.8050x; 1.8050x over previous
#include <cuda_runtime.h>
#include <cuda_bf16.h>

// Problem shapes (fixed by the dataset):
//   text:        [16, 2048, 256] f32      d_in[0]
//   const_mat:   [16, 2048, 2048] i32     d_in[1]   (UNUSED: softmax rows sum to 1)
//   const_labels:[16, 2048, 8] i32        d_in[2]
//   emb_table:   [100, 128] f32           d_in[3]
//   attn_W:      [256, 384] f32           d_in[4]   (UNUSED: cancels in softmax)
//   attn_b:      [256] f32                d_in[5]   (UNUSED)
//   fc_W:        [256, 128] f32           d_in[6]
//   fc_b:        [256] f32                d_in[7]
//   out:         [16, 2048, 256] f32
//
// Math collapse: out[pos,d] = relu( text[pos,d] + sum_{k=0..7} G[labels[pos,k], d] )
// with G[n,d] = 0.125 * (fc_b[d] + emb_table[n] . fc_W[d]).
//
// R2: no shared memory. G (100 KB) lives in L1 (228 KB with zero smem carveout).
// One thread per output float4 -> full occupancy, 8 independent gather loads
// per thread for MLP. Kernel should approach the 67 MB HBM traffic floor.

#define CN    100
#define CD    128
#define DIM   256
#define KLBL  8
#define D4    (DIM / 4)          // 64 float4 per position

__device__ float g_G[CN * DIM];  // 100 KB precomputed table

// ---------------------------------------------------------------------------
// Kernel A: G[n,d] = 0.125 * (fc_b[d] + sum_c emb_table[n,c] * fc_W[d,c])
// ---------------------------------------------------------------------------
__global__ void __launch_bounds__(DIM) build_G_kernel(
    const float* __restrict__ emb_table,
    const float* __restrict__ fc_W,
    const float* __restrict__ fc_b)
{
    __shared__ float se[CD];
    const int n = blockIdx.x;
    const int d = threadIdx.x;
    if (d < CD) se[d] = emb_table[n * CD + d];
    __syncthreads();

    const float4* w4 = reinterpret_cast<const float4*>(fc_W + d * CD);
    float acc = fc_b[d];
    #pragma unroll
    for (int c4 = 0; c4 < CD / 4; c4++) {
        float4 w = w4[c4];
        acc = fmaf(se[c4 * 4 + 0], w.x, acc);
        acc = fmaf(se[c4 * 4 + 1], w.y, acc);
        acc = fmaf(se[c4 * 4 + 2], w.z, acc);
        acc = fmaf(se[c4 * 4 + 3], w.w, acc);
    }
    g_G[n * DIM + d] = 0.125f * acc;
}

// ---------------------------------------------------------------------------
// Kernel B: fused gather-add-relu, one thread per float4 of the output.
// gid -> (pos = gid/64, d4 = gid%64). All 32 lanes of a warp share `pos`
// (warp spans 128 consecutive d's), so label loads are uniform broadcasts.
// ---------------------------------------------------------------------------
__global__ void __launch_bounds__(256) fused_gather_kernel(
    const float4* __restrict__ text4,
    const int*    __restrict__ labels,
    float4*       __restrict__ out4,
    int n4total)
{
    const int gid = blockIdx.x * blockDim.x + threadIdx.x;
    if (gid >= n4total) return;

    const int pos = gid >> 6;        // position index
    const int d4  = gid & (D4 - 1);  // float4 index within the 256-dim row

    // 8 labels: two uniform int4 loads (32B aligned)
    const int4* lb = reinterpret_cast<const int4*>(labels + pos * KLBL);
    const int4 l0 = __ldg(lb + 0);
    const int4 l1 = __ldg(lb + 1);

    const float4* __restrict__ G4 = reinterpret_cast<const float4*>(g_G);

    // Issue all 9 loads up front (independent -> MLP), then reduce.
    float4 t  = __ldg(text4 + gid);
    float4 g0 = __ldg(G4 + l0.x * D4 + d4);
    float4 g1 = __ldg(G4 + l0.y * D4 + d4);
    float4 g2 = __ldg(G4 + l0.z * D4 + d4);
    float4 g3 = __ldg(G4 + l0.w * D4 + d4);
    float4 g4 = __ldg(G4 + l1.x * D4 + d4);
    float4 g5 = __ldg(G4 + l1.y * D4 + d4);
    float4 g6 = __ldg(G4 + l1.z * D4 + d4);
    float4 g7 = __ldg(G4 + l1.w * D4 + d4);

    float4 r;
    r.x = fmaxf(t.x + ((g0.x + g1.x) + (g2.x + g3.x)) + ((g4.x + g5.x) + (g6.x + g7.x)), 0.0f);
    r.y = fmaxf(t.y + ((g0.y + g1.y) + (g2.y + g3.y)) + ((g4.y + g5.y) + (g6.y + g7.y)), 0.0f);
    r.z = fmaxf(t.z + ((g0.z + g1.z) + (g2.z + g3.z)) + ((g4.z + g5.z) + (g6.z + g7.z)), 0.0f);
    r.w = fmaxf(t.w + ((g0.w + g1.w) + (g2.w + g3.w)) + ((g4.w + g5.w) + (g6.w + g7.w)), 0.0f);

    out4[gid] = r;
}

// ---------------------------------------------------------------------------
extern "C" void kernel_launch(void* const* d_in, const int* in_sizes, int n_in,
                              void* d_out, int out_size)
{
    const float* text      = (const float*)d_in[0];
    const int*   labels    = (const int*)  d_in[2];
    const float* emb_table = (const float*)d_in[3];
    const float* fc_W      = (const float*)d_in[6];
    const float* fc_b      = (const float*)d_in[7];
    float*       out       = (float*)d_out;

    const int ntotal  = in_sizes[0];      // 16*2048*256 = 8,388,608
    const int n4total = ntotal / 4;       // 2,097,152 float4s

    build_G_kernel<<<CN, DIM>>>(emb_table, fc_W, fc_b);

    const int block = 256;
    const int grid  = (n4total + block - 1) / block;   // 8192
    fused_gather_kernel<<<grid, block>>>(
        reinterpret_cast<const float4*>(text),
        labels,
        reinterpret_cast<float4*>(out),
        n4total);
}